// round 1
// baseline (speedup 1.0000x reference)
#include <cuda_runtime.h>
#include <cuda_bf16.h>

#define NPTS 262144
#define THREADS 128
#define NBLOCKS (NPTS / THREADS)

// Hash-grid resolutions: floor(16 * (2048/16)^(l/15)), matches the numpy reference.
__constant__ float c_res[16] = {
    16.f, 22.f, 30.f, 42.f, 58.f, 80.f, 111.f, 153.f,
    212.f, 294.f, 406.f, 561.f, 776.f, 1072.f, 1482.f, 2048.f
};

// Shared-memory weight layout (floats):
//   [0,2048)     xyz_w0   row-major (64x32)
//   [2048,3072)  xyz_woutT transposed (64x16): [j*16+o] = wout[o*64+j]
//   [3072,5120)  rgb_w0   row-major (64x32)
//   [5120,9216)  rgb_w1T  transposed (64x64): [j*64+o] = r1[o*64+j]
//   [9216,9408)  rgb_wout row-major (3x64)

__global__ __launch_bounds__(THREADS, 3)
void ngp_fused(const float* __restrict__ gx, const float* __restrict__ gd,
               const float2* __restrict__ tab,
               const float* __restrict__ w0, const float* __restrict__ wout,
               const float* __restrict__ r0, const float* __restrict__ r1,
               const float* __restrict__ rout, float* __restrict__ out)
{
    __shared__ float s[9408];
    const int tid = threadIdx.x;
    for (int i = tid; i < 2048; i += THREADS) s[i] = w0[i];
    for (int i = tid; i < 1024; i += THREADS) { int o = i >> 6, j = i & 63; s[2048 + j*16 + o] = wout[i]; }
    for (int i = tid; i < 2048; i += THREADS) s[3072 + i] = r0[i];
    for (int i = tid; i < 4096; i += THREADS) { int o = i >> 6, j = i & 63; s[5120 + j*64 + o] = r1[i]; }
    for (int i = tid; i < 192;  i += THREADS) s[9216 + i] = rout[i];
    __syncthreads();

    const int n = blockIdx.x * THREADS + tid;

    // ---- Phase 1: hash-grid encode -> emb[32] ----
    const float x0 = gx[3*n]     + 0.5f;
    const float x1 = gx[3*n + 1] + 0.5f;
    const float x2 = gx[3*n + 2] + 0.5f;

    float emb[32];
    #pragma unroll
    for (int l = 0; l < 16; l++) {
        const float r = c_res[l];
        float p0 = x0 * r, p1 = x1 * r, p2 = x2 * r;
        float f0 = floorf(p0), f1 = floorf(p1), f2 = floorf(p2);
        float a0 = p0 - f0, a1 = p1 - f1, a2 = p2 - f2;
        float b0 = 1.f - a0, b1 = 1.f - a1, b2 = 1.f - a2;
        unsigned u0 = (unsigned)f0, u1 = (unsigned)f1, u2 = (unsigned)f2;
        unsigned hx[2] = { u0, u0 + 1u };
        unsigned hy[2] = { u1 * 2654435761u, (u1 + 1u) * 2654435761u };
        unsigned hz[2] = { u2 * 805459861u,  (u2 + 1u) * 805459861u };
        const unsigned base = ((unsigned)l) << 19;

        float2 v[8];
        float  wt[8];
        #pragma unroll
        for (int c = 0; c < 8; c++) {
            unsigned h = ((hx[(c >> 2) & 1] ^ hy[(c >> 1) & 1] ^ hz[c & 1]) & ((1u << 19) - 1u)) + base;
            v[c]  = __ldg(&tab[h]);
            wt[c] = ((c & 4) ? a0 : b0) * ((c & 2) ? a1 : b1) * ((c & 1) ? a2 : b2);
        }
        float e0 = 0.f, e1 = 0.f;
        #pragma unroll
        for (int c = 0; c < 8; c++) {
            e0 = fmaf(wt[c], v[c].x, e0);
            e1 = fmaf(wt[c], v[c].y, e1);
        }
        emb[2*l]     = e0;
        emb[2*l + 1] = e1;
    }

    // ---- Phase 2: xyz MLP: emb(32) -> relu(64) -> h(16); sigma = exp(h[0]) ----
    float h[16];
    #pragma unroll
    for (int o = 0; o < 16; o++) h[o] = 0.f;

    #pragma unroll 4
    for (int j = 0; j < 64; j++) {
        float acc = 0.f;
        #pragma unroll
        for (int i = 0; i < 32; i += 4) {
            float4 w = *reinterpret_cast<const float4*>(&s[j*32 + i]);
            acc = fmaf(emb[i],   w.x, acc);
            acc = fmaf(emb[i+1], w.y, acc);
            acc = fmaf(emb[i+2], w.z, acc);
            acc = fmaf(emb[i+3], w.w, acc);
        }
        acc = fmaxf(acc, 0.f);
        #pragma unroll
        for (int o = 0; o < 16; o += 4) {
            float4 w = *reinterpret_cast<const float4*>(&s[2048 + j*16 + o]);
            h[o]   = fmaf(acc, w.x, h[o]);
            h[o+1] = fmaf(acc, w.y, h[o+1]);
            h[o+2] = fmaf(acc, w.z, h[o+2]);
            h[o+3] = fmaf(acc, w.w, h[o+3]);
        }
    }
    out[n] = expf(h[0]);

    // ---- Phase 3: SH deg-4 of normalized d -> f[0..16); f[16..32) = h ----
    const float d0 = gd[3*n], d1 = gd[3*n + 1], d2 = gd[3*n + 2];
    const float inv = rsqrtf(fmaf(d0, d0, fmaf(d1, d1, d2 * d2)));
    const float sx = d0 * inv, sy = d1 * inv, sz = d2 * inv;
    const float xx = sx*sx, yy = sy*sy, zz = sz*sz;
    const float xy = sx*sy, yz = sy*sz, xz = sx*sz;

    float f[32];
    f[0]  = 0.28209479177387814f;
    f[1]  = -0.4886025119029199f * sy;
    f[2]  =  0.4886025119029199f * sz;
    f[3]  = -0.4886025119029199f * sx;
    f[4]  =  1.0925484305920792f * xy;
    f[5]  = -1.0925484305920792f * yz;
    f[6]  =  0.31539156525252005f * (3.0f * zz - 1.0f);
    f[7]  = -1.0925484305920792f * xz;
    f[8]  =  0.5462742152960396f * (xx - yy);
    f[9]  = -0.5900435899266435f * sy * (3.0f * xx - yy);
    f[10] =  2.890611442640554f  * xy * sz;
    f[11] = -0.4570457994644658f * sy * (4.0f * zz - xx - yy);
    f[12] =  0.3731763325901154f * sz * (2.0f * zz - 3.0f * xx - 3.0f * yy);
    f[13] = -0.4570457994644658f * sx * (4.0f * zz - xx - yy);
    f[14] =  1.445305721320277f  * sz * (xx - yy);
    f[15] = -0.5900435899266435f * sx * (xx - 3.0f * yy);
    #pragma unroll
    for (int o = 0; o < 16; o++) f[16 + o] = h[o];

    // ---- Phase 4: rgb MLP layers 0+1 fused: f(32) -> relu(64) -> b(64) ----
    float b[64];
    #pragma unroll
    for (int o = 0; o < 64; o++) b[o] = 0.f;

    #pragma unroll 2
    for (int j = 0; j < 64; j++) {
        float acc = 0.f;
        #pragma unroll
        for (int i = 0; i < 32; i += 4) {
            float4 w = *reinterpret_cast<const float4*>(&s[3072 + j*32 + i]);
            acc = fmaf(f[i],   w.x, acc);
            acc = fmaf(f[i+1], w.y, acc);
            acc = fmaf(f[i+2], w.z, acc);
            acc = fmaf(f[i+3], w.w, acc);
        }
        acc = fmaxf(acc, 0.f);
        #pragma unroll
        for (int o = 0; o < 64; o += 4) {
            float4 w = *reinterpret_cast<const float4*>(&s[5120 + j*64 + o]);
            b[o]   = fmaf(acc, w.x, b[o]);
            b[o+1] = fmaf(acc, w.y, b[o+1]);
            b[o+2] = fmaf(acc, w.z, b[o+2]);
            b[o+3] = fmaf(acc, w.w, b[o+3]);
        }
    }

    // ---- Phase 5: output layer (64 -> 3) + sigmoid ----
    float r0a = 0.f, r1a = 0.f, r2a = 0.f;
    #pragma unroll
    for (int o = 0; o < 64; o++) {
        const float bo = fmaxf(b[o], 0.f);
        r0a = fmaf(bo, s[9216 + o],       r0a);
        r1a = fmaf(bo, s[9216 + 64 + o],  r1a);
        r2a = fmaf(bo, s[9216 + 128 + o], r2a);
    }
    float* orgb = out + NPTS;
    orgb[3*n]     = 1.f / (1.f + expf(-r0a));
    orgb[3*n + 1] = 1.f / (1.f + expf(-r1a));
    orgb[3*n + 2] = 1.f / (1.f + expf(-r2a));
}

extern "C" void kernel_launch(void* const* d_in, const int* in_sizes, int n_in,
                              void* d_out, int out_size)
{
    ngp_fused<<<NBLOCKS, THREADS>>>(
        (const float*)d_in[0],   // x (N,3)
        (const float*)d_in[1],   // d (N,3)
        (const float2*)d_in[2],  // table (16, 2^19, 2)
        (const float*)d_in[3],   // xyz_w0 (64,32)
        (const float*)d_in[4],   // xyz_wout (16,64)
        (const float*)d_in[5],   // rgb_w0 (64,32)
        (const float*)d_in[6],   // rgb_w1 (64,64)
        (const float*)d_in[7],   // rgb_wout (3,64)
        (float*)d_out);
}

// round 2
// speedup vs baseline: 1.2610x; 1.2610x over previous
#include <cuda_runtime.h>
#include <cuda_bf16.h>

#define NPTS 262144
#define THREADS 128
#define NBLOCKS (NPTS / THREADS)

typedef unsigned long long u64;

// Hash-grid resolutions: floor(16 * (2048/16)^(l/15)), matches the numpy reference.
__constant__ float c_res[16] = {
    16.f, 22.f, 30.f, 42.f, 58.f, 80.f, 111.f, 153.f,
    212.f, 294.f, 406.f, 561.f, 776.f, 1072.f, 1482.f, 2048.f
};

// ---- packed fp32x2 helpers (Blackwell packed-FP32 pipe; ptxas won't auto-fuse) ----
__device__ __forceinline__ void fma2(u64 &d, u64 a, u64 b) {
    asm("fma.rn.f32x2 %0, %1, %2, %0;" : "+l"(d) : "l"(a), "l"(b));
}
__device__ __forceinline__ u64 pack2(float lo, float hi) {
    u64 r; asm("mov.b64 %0, {%1, %2};" : "=l"(r) : "f"(lo), "f"(hi)); return r;
}
__device__ __forceinline__ float hadd2(u64 v) {
    float lo, hi; asm("mov.b64 {%0, %1}, %2;" : "=f"(lo), "=f"(hi) : "l"(v)); return lo + hi;
}

// Shared-memory weight layout (floats):
//   [0,2048)     xyz_w0    row-major (64x32)
//   [2048,3072)  xyz_woutT transposed (64x16): [j*16+o] = wout[o*64+j]
//   [3072,5120)  rgb_w0    row-major (64x32)
//   [5120,9216)  rgb_w1    row-major (64x64)  (gather form -> no transpose)
//   [9216,9408)  rgb_wout  row-major (3x64)

__global__ __launch_bounds__(THREADS, 4)
void ngp_fused(const float* __restrict__ gx, const float* __restrict__ gd,
               const float2* __restrict__ tab,
               const float* __restrict__ w0, const float* __restrict__ wout,
               const float* __restrict__ r0, const float* __restrict__ r1,
               const float* __restrict__ rout, float* __restrict__ out)
{
    __shared__ __align__(16) float s[9408];
    const int tid = threadIdx.x;
    for (int i = tid; i < 2048; i += THREADS) s[i] = w0[i];
    for (int i = tid; i < 1024; i += THREADS) { int o = i >> 6, j = i & 63; s[2048 + j*16 + o] = wout[i]; }
    for (int i = tid; i < 2048; i += THREADS) s[3072 + i] = r0[i];
    for (int i = tid; i < 4096; i += THREADS) s[5120 + i] = r1[i];
    for (int i = tid; i < 192;  i += THREADS) s[9216 + i] = rout[i];
    __syncthreads();

    const int n = blockIdx.x * THREADS + tid;

    // ---- Phase 1: hash-grid encode -> empack[16] (one f32x2 pair per level) ----
    const float x0 = gx[3*n]     + 0.5f;
    const float x1 = gx[3*n + 1] + 0.5f;
    const float x2 = gx[3*n + 2] + 0.5f;

    u64 empack[16];
    #pragma unroll
    for (int l = 0; l < 16; l++) {
        const float r = c_res[l];
        float p0 = x0 * r, p1 = x1 * r, p2 = x2 * r;
        float f0 = floorf(p0), f1 = floorf(p1), f2 = floorf(p2);
        float a0 = p0 - f0, a1 = p1 - f1, a2 = p2 - f2;
        float b0 = 1.f - a0, b1 = 1.f - a1, b2 = 1.f - a2;
        unsigned u0 = (unsigned)f0, u1 = (unsigned)f1, u2 = (unsigned)f2;
        unsigned hx[2] = { u0, u0 + 1u };
        unsigned hy[2] = { u1 * 2654435761u, (u1 + 1u) * 2654435761u };
        unsigned hz[2] = { u2 * 805459861u,  (u2 + 1u) * 805459861u };
        const unsigned base = ((unsigned)l) << 19;

        float2 v[8];
        float  wt[8];
        #pragma unroll
        for (int c = 0; c < 8; c++) {
            unsigned h = ((hx[(c >> 2) & 1] ^ hy[(c >> 1) & 1] ^ hz[c & 1]) & ((1u << 19) - 1u)) + base;
            v[c]  = __ldg(&tab[h]);
            wt[c] = ((c & 4) ? a0 : b0) * ((c & 2) ? a1 : b1) * ((c & 1) ? a2 : b2);
        }
        float e0 = 0.f, e1 = 0.f;
        #pragma unroll
        for (int c = 0; c < 8; c++) {
            e0 = fmaf(wt[c], v[c].x, e0);
            e1 = fmaf(wt[c], v[c].y, e1);
        }
        empack[l] = pack2(e0, e1);
    }

    // ---- Phase 2: xyz MLP: emb(32) -> relu(64) -> h2[8] (16 outs, packed) ----
    u64 h2[8];
    #pragma unroll
    for (int k = 0; k < 8; k++) h2[k] = 0ull;

    #pragma unroll 2
    for (int jp = 0; jp < 32; jp++) {
        const int j0 = 2*jp;
        u64 acc0 = 0ull, acc1 = 0ull;
        const ulonglong2* wr0 = reinterpret_cast<const ulonglong2*>(&s[j0*32]);
        const ulonglong2* wr1 = reinterpret_cast<const ulonglong2*>(&s[j0*32 + 32]);
        #pragma unroll
        for (int i = 0; i < 8; i++) {
            ulonglong2 wa = wr0[i];
            fma2(acc0, empack[2*i],   wa.x);
            fma2(acc0, empack[2*i+1], wa.y);
            ulonglong2 wb = wr1[i];
            fma2(acc1, empack[2*i],   wb.x);
            fma2(acc1, empack[2*i+1], wb.y);
        }
        const float a0 = fmaxf(hadd2(acc0), 0.f);
        const float a1 = fmaxf(hadd2(acc1), 0.f);
        const u64 p0 = pack2(a0, a0);
        const u64 p1 = pack2(a1, a1);
        const ulonglong2* wo0 = reinterpret_cast<const ulonglong2*>(&s[2048 + j0*16]);
        const ulonglong2* wo1 = reinterpret_cast<const ulonglong2*>(&s[2048 + j0*16 + 16]);
        #pragma unroll
        for (int k = 0; k < 4; k++) {
            ulonglong2 wa = wo0[k];
            fma2(h2[2*k],   p0, wa.x);
            fma2(h2[2*k+1], p0, wa.y);
            ulonglong2 wb = wo1[k];
            fma2(h2[2*k],   p1, wb.x);
            fma2(h2[2*k+1], p1, wb.y);
        }
    }
    {
        float hlo, hhi;
        asm("mov.b64 {%0, %1}, %2;" : "=f"(hlo), "=f"(hhi) : "l"(h2[0]));
        out[n] = expf(hlo);
    }

    // ---- Phase 3: SH deg-4 -> fpack[0..8); fpack[8..16) = h2 ----
    const float d0 = gd[3*n], d1 = gd[3*n + 1], d2 = gd[3*n + 2];
    const float inv = rsqrtf(fmaf(d0, d0, fmaf(d1, d1, d2 * d2)));
    const float sx = d0 * inv, sy = d1 * inv, sz = d2 * inv;
    const float xx = sx*sx, yy = sy*sy, zz = sz*sz;
    const float xy = sx*sy, yz = sy*sz, xz = sx*sz;

    u64 fpack[16];
    fpack[0] = pack2(0.28209479177387814f, -0.4886025119029199f * sy);
    fpack[1] = pack2( 0.4886025119029199f * sz, -0.4886025119029199f * sx);
    fpack[2] = pack2( 1.0925484305920792f * xy, -1.0925484305920792f * yz);
    fpack[3] = pack2( 0.31539156525252005f * (3.0f * zz - 1.0f), -1.0925484305920792f * xz);
    fpack[4] = pack2( 0.5462742152960396f * (xx - yy),
                      -0.5900435899266435f * sy * (3.0f * xx - yy));
    fpack[5] = pack2( 2.890611442640554f  * xy * sz,
                      -0.4570457994644658f * sy * (4.0f * zz - xx - yy));
    fpack[6] = pack2( 0.3731763325901154f * sz * (2.0f * zz - 3.0f * xx - 3.0f * yy),
                      -0.4570457994644658f * sx * (4.0f * zz - xx - yy));
    fpack[7] = pack2( 1.445305721320277f  * sz * (xx - yy),
                      -0.5900435899266435f * sx * (xx - 3.0f * yy));
    #pragma unroll
    for (int k = 0; k < 8; k++) fpack[8 + k] = h2[k];

    // ---- Phase 4a: rgb layer0: f(32) -> relu -> a2[32] (64 outs, packed pairs) ----
    u64 a2[32];
    #pragma unroll 2
    for (int jp = 0; jp < 32; jp++) {
        const int j0 = 2*jp;
        u64 acc0 = 0ull, acc1 = 0ull;
        const ulonglong2* wr0 = reinterpret_cast<const ulonglong2*>(&s[3072 + j0*32]);
        const ulonglong2* wr1 = reinterpret_cast<const ulonglong2*>(&s[3072 + j0*32 + 32]);
        #pragma unroll
        for (int i = 0; i < 8; i++) {
            ulonglong2 wa = wr0[i];
            fma2(acc0, fpack[2*i],   wa.x);
            fma2(acc0, fpack[2*i+1], wa.y);
            ulonglong2 wb = wr1[i];
            fma2(acc1, fpack[2*i],   wb.x);
            fma2(acc1, fpack[2*i+1], wb.y);
        }
        a2[jp] = pack2(fmaxf(hadd2(acc0), 0.f), fmaxf(hadd2(acc1), 0.f));
    }

    // ---- Phase 4b: rgb layer1 + output layer, one output-pair at a time ----
    u64 racc0 = 0ull, racc1 = 0ull, racc2 = 0ull;
    #pragma unroll 2
    for (int op = 0; op < 32; op++) {
        const int o0 = 2*op;
        u64 t0 = 0ull, t1 = 0ull;
        const ulonglong2* wr0 = reinterpret_cast<const ulonglong2*>(&s[5120 + o0*64]);
        const ulonglong2* wr1 = reinterpret_cast<const ulonglong2*>(&s[5120 + o0*64 + 64]);
        #pragma unroll
        for (int i = 0; i < 16; i++) {
            ulonglong2 wa = wr0[i];
            fma2(t0, a2[2*i],   wa.x);
            fma2(t0, a2[2*i+1], wa.y);
            ulonglong2 wb = wr1[i];
            fma2(t1, a2[2*i],   wb.x);
            fma2(t1, a2[2*i+1], wb.y);
        }
        const float b0 = fmaxf(hadd2(t0), 0.f);
        const float b1 = fmaxf(hadd2(t1), 0.f);
        const u64 bp = pack2(b0, b1);
        fma2(racc0, bp, *reinterpret_cast<const u64*>(&s[9216 + o0]));
        fma2(racc1, bp, *reinterpret_cast<const u64*>(&s[9216 + 64 + o0]));
        fma2(racc2, bp, *reinterpret_cast<const u64*>(&s[9216 + 128 + o0]));
    }

    const float rr0 = hadd2(racc0);
    const float rr1 = hadd2(racc1);
    const float rr2 = hadd2(racc2);
    float* orgb = out + NPTS;
    orgb[3*n]     = 1.f / (1.f + expf(-rr0));
    orgb[3*n + 1] = 1.f / (1.f + expf(-rr1));
    orgb[3*n + 2] = 1.f / (1.f + expf(-rr2));
}

extern "C" void kernel_launch(void* const* d_in, const int* in_sizes, int n_in,
                              void* d_out, int out_size)
{
    ngp_fused<<<NBLOCKS, THREADS>>>(
        (const float*)d_in[0],   // x (N,3)
        (const float*)d_in[1],   // d (N,3)
        (const float2*)d_in[2],  // table (16, 2^19, 2)
        (const float*)d_in[3],   // xyz_w0 (64,32)
        (const float*)d_in[4],   // xyz_wout (16,64)
        (const float*)d_in[5],   // rgb_w0 (64,32)
        (const float*)d_in[6],   // rgb_w1 (64,64)
        (const float*)d_in[7],   // rgb_wout (3,64)
        (float*)d_out);
}